// round 3
// baseline (speedup 1.0000x reference)
#include <cuda_runtime.h>
#include <math.h>

#define L_LAYERS 3
#define D_DIM    128
#define A_DIM    64
#define NREL     401
#define N_NODE   100000
#define N_EDGE   600000
#define NQ_C     512
#define N_DELTA  731
#define MAX_OUT  (512*50000)

// ---------------- static device scratch (no allocations allowed) ----------------
__device__ float g_hprev  [N_NODE * D_DIM];
__device__ float g_hidden1[N_NODE * D_DIM];
__device__ float g_agg    [N_NODE * D_DIM];
__device__ float g_gi     [N_NODE * 3 * D_DIM];
__device__ float g_gh     [N_NODE * 3 * D_DIM];
__device__ float g_HS     [N_NODE * A_DIM];
__device__ float g_Rattn  [NREL * A_DIM];
__device__ float g_Qattn  [NQ_C * A_DIM];
__device__ float g_Hattn  [N_DELTA * A_DIM];
__device__ float g_Hmsg   [N_DELTA * D_DIM];
__device__ int   g_winner [MAX_OUT];

__device__ __forceinline__ float sigmoidf_(float x) { return 1.0f / (1.0f + expf(-x)); }

// ---------------- per-relation / per-query attention tables ----------------
// block b < NREL : Rattn[b][a]   = rela_l[b]        . Wr[a]
// block b >= NREL: Qattn[b-NREL][a] = rela_l[q_rel[q]] . Wqr_w[a] + Wqr_b[a]
__global__ void k_tab_rq(const float* __restrict__ rela_l,
                         const float* __restrict__ Wr_l,
                         const float* __restrict__ Wqr_w_l,
                         const float* __restrict__ Wqr_b_l,
                         const int*   __restrict__ q_rel,
                         float* __restrict__ Rattn,
                         float* __restrict__ Qattn)
{
    __shared__ float hv[128];
    int b = blockIdx.x;
    int a = threadIdx.x; // 0..63
    const float* src = (b < NREL) ? (rela_l + (size_t)b * 128)
                                  : (rela_l + (size_t)q_rel[b - NREL] * 128);
    hv[a] = src[a];
    hv[a + 64] = src[a + 64];
    __syncthreads();
    const float* W = ((b < NREL) ? Wr_l : Wqr_w_l) + (size_t)a * 128;
    float s = 0.f;
#pragma unroll
    for (int k = 0; k < 128; k += 4) {
        float4 w = *(const float4*)(W + k);
        s += hv[k] * w.x + hv[k + 1] * w.y + hv[k + 2] * w.z + hv[k + 3] * w.w;
    }
    if (b < NREL) Rattn[b * 64 + a] = s;
    else          Qattn[(b - NREL) * 64 + a] = s + Wqr_b_l[a];
}

// ---------------- per-delta tables: h_hau vector + h_hau @ Wtau^T ----------------
__global__ void k_tab_delta(const float* __restrict__ wt1, const float* __restrict__ bt1,
                            const float* __restrict__ wt2, const float* __restrict__ bt2,
                            const float* __restrict__ Wtau_l,
                            float* __restrict__ Hmsg, float* __restrict__ Hattn)
{
    __shared__ float hh[128];
    int di = blockIdx.x;           // 0..730
    float delta = (float)(di - 365);
    int d = threadIdx.x;           // 0..127
    float v = wt1[d] * delta + bt1[d] + sinf(wt2[d] * delta + bt2[d]);
    hh[d] = v;
    Hmsg[(size_t)di * 128 + d] = v;
    __syncthreads();
    if (d < 64) {
        const float* W = Wtau_l + (size_t)d * 128;
        float s = 0.f;
#pragma unroll
        for (int k = 0; k < 128; k += 4) {
            float4 w = *(const float4*)(W + k);
            s += hh[k] * w.x + hh[k + 1] * w.y + hh[k + 2] * w.z + hh[k + 3] * w.w;
        }
        Hattn[(size_t)di * 64 + d] = s;
    }
}

// ---------------- edge kernel: one warp per edge ----------------
__global__ void __launch_bounds__(256) k_edge(
    const int* __restrict__ e_sub, const int* __restrict__ e_rel,
    const int* __restrict__ e_obj, const int* __restrict__ e_ridx,
    const int* __restrict__ e_tau, const int* __restrict__ q_tau,
    const float* __restrict__ HS, const float* __restrict__ Rattn,
    const float* __restrict__ Qattn, const float* __restrict__ Hattn,
    const float* __restrict__ Hmsg, const float* __restrict__ hprev,
    const float* __restrict__ rela_l, const float* __restrict__ walpha_w_l,
    const float* __restrict__ walpha_b_l, float* __restrict__ agg)
{
    int e = (int)((blockIdx.x * blockDim.x + threadIdx.x) >> 5);
    int lane = threadIdx.x & 31;
    if (e >= N_EDGE) return;

    int s_ = e_sub[e];
    int r_ = e_rel[e];
    int o_ = e_obj[e];
    int q_ = e_ridx[e];
    int t_ = e_tau[e];
    int tq = q_tau[q_];
    int tau = (t_ >= 0) ? t_ : tq;
    int di = tau - tq + 365;
    di = min(max(di, 0), 730);

    // attention: 64 dims, 2 per lane (float2)
    float2 hs2 = ((const float2*)HS)   [(size_t)s_ * 32 + lane];
    float2 rr2 = ((const float2*)Rattn)[(size_t)r_ * 32 + lane];
    float2 qq2 = ((const float2*)Qattn)[(size_t)q_ * 32 + lane];
    float2 tt2 = ((const float2*)Hattn)[(size_t)di * 32 + lane];
    float vx = fmaxf(hs2.x + rr2.x + qq2.x + tt2.x, 0.f);
    float vy = fmaxf(hs2.y + rr2.y + qq2.y + tt2.y, 0.f);
    float2 wa = ((const float2*)walpha_w_l)[lane];
    float acc = vx * wa.x + vy * wa.y;
#pragma unroll
    for (int off = 16; off; off >>= 1) acc += __shfl_xor_sync(0xffffffffu, acc, off);
    float alpha = 1.0f / (1.0f + expf(-(acc + walpha_b_l[0])));

    // message: 128 dims, float4 per lane
    float4 h4 = ((const float4*)hprev) [(size_t)s_ * 32 + lane];
    float4 r4 = ((const float4*)rela_l)[(size_t)r_ * 32 + lane];
    float4 m4 = ((const float4*)Hmsg)  [(size_t)di * 32 + lane];
    float mx = alpha * (h4.x + r4.x + m4.x);
    float my = alpha * (h4.y + r4.y + m4.y);
    float mz = alpha * (h4.z + r4.z + m4.z);
    float mw = alpha * (h4.w + r4.w + m4.w);
    float* dst = agg + (size_t)o_ * 128 + lane * 4;
    asm volatile("red.global.add.v4.f32 [%0], {%1,%2,%3,%4};"
                 :: "l"(dst), "f"(mx), "f"(my), "f"(mz), "f"(mw) : "memory");
}

// ---------------- SGEMM: C[M,NOUT] = A[M,128] @ W[NOUT,128]^T (+bias)(+relu) ----------------
// BM=BN=128, BK=8, 256 threads, 8x8 per-thread tile (compute-bound on FFMA pipe)
__global__ void __launch_bounds__(256) k_sgemm(
    const float* __restrict__ A, const float* __restrict__ W,
    const float* __restrict__ bias, float* __restrict__ C,
    int M, int NOUT, int relu)
{
    __shared__ float As[8][128];
    __shared__ float Bs[8][128];
    int bm = blockIdx.x * 128;
    int bn = blockIdx.y * 128;
    int tid = threadIdx.x;
    int lr = tid >> 1;            // 0..127 row-in-tile for loads
    int lc = (tid & 1) * 4;       // 0 or 4  k-offset for loads
    int tm = (tid >> 4) * 8;      // 0..120
    int tn = (tid & 15) * 8;      // 0..120
    bool aval = (bm + lr) < M;
    bool bval = (bn + lr) < NOUT;
    const float* Ap = A + (size_t)(bm + lr) * 128 + lc;
    const float* Bp = W + (size_t)(bn + lr) * 128 + lc;

    float acc[8][8];
#pragma unroll
    for (int i = 0; i < 8; i++)
#pragma unroll
        for (int j = 0; j < 8; j++) acc[i][j] = 0.f;

    for (int kt = 0; kt < 128; kt += 8) {
        float4 a4 = aval ? *(const float4*)(Ap + kt) : make_float4(0.f, 0.f, 0.f, 0.f);
        float4 b4 = bval ? *(const float4*)(Bp + kt) : make_float4(0.f, 0.f, 0.f, 0.f);
        As[lc + 0][lr] = a4.x; As[lc + 1][lr] = a4.y; As[lc + 2][lr] = a4.z; As[lc + 3][lr] = a4.w;
        Bs[lc + 0][lr] = b4.x; Bs[lc + 1][lr] = b4.y; Bs[lc + 2][lr] = b4.z; Bs[lc + 3][lr] = b4.w;
        __syncthreads();
#pragma unroll
        for (int kk = 0; kk < 8; kk++) {
            float4 a0 = *(const float4*)&As[kk][tm];
            float4 a1 = *(const float4*)&As[kk][tm + 4];
            float4 b0 = *(const float4*)&Bs[kk][tn];
            float4 b1 = *(const float4*)&Bs[kk][tn + 4];
            float av[8] = {a0.x, a0.y, a0.z, a0.w, a1.x, a1.y, a1.z, a1.w};
            float bv[8] = {b0.x, b0.y, b0.z, b0.w, b1.x, b1.y, b1.z, b1.w};
#pragma unroll
            for (int i = 0; i < 8; i++)
#pragma unroll
                for (int j = 0; j < 8; j++)
                    acc[i][j] = fmaf(av[i], bv[j], acc[i][j]);
        }
        __syncthreads();
    }

#pragma unroll
    for (int i = 0; i < 8; i++) {
        int row = bm + tm + i;
        if (row >= M) break;
#pragma unroll
        for (int j = 0; j < 8; j += 4) {
            int col = bn + tn + j;
            if (col >= NOUT) break;
            float4 v = make_float4(acc[i][j], acc[i][j + 1], acc[i][j + 2], acc[i][j + 3]);
            if (bias) {
                v.x += bias[col]; v.y += bias[col + 1]; v.z += bias[col + 2]; v.w += bias[col + 3];
            }
            if (relu) {
                v.x = fmaxf(v.x, 0.f); v.y = fmaxf(v.y, 0.f);
                v.z = fmaxf(v.z, 0.f); v.w = fmaxf(v.w, 0.f);
            }
            *(float4*)(C + (size_t)row * NOUT + col) = v;
        }
    }
}

// ---------------- GRU elementwise (PyTorch semantics), in-place on h ----------------
__global__ void k_gru(const float* __restrict__ gi, const float* __restrict__ gh,
                      float* __restrict__ h)
{
    int idx = blockIdx.x * blockDim.x + threadIdx.x;  // node*32 + g
    if (idx >= N_NODE * 32) return;
    int n = idx >> 5, g = idx & 31;
    const float4* gi4 = (const float4*)(gi + (size_t)n * 384);
    const float4* gh4 = (const float4*)(gh + (size_t)n * 384);
    float4 ir = gi4[g],      iz = gi4[32 + g], in_ = gi4[64 + g];
    float4 hr = gh4[g],      hz = gh4[32 + g], hn  = gh4[64 + g];
    float4 h0 = ((const float4*)h)[(size_t)n * 32 + g];
    float4 out;
    {
        float r = sigmoidf_(ir.x + hr.x), z = sigmoidf_(iz.x + hz.x);
        float nn = tanhf(in_.x + r * hn.x);
        out.x = (1.f - z) * nn + z * h0.x;
    }
    {
        float r = sigmoidf_(ir.y + hr.y), z = sigmoidf_(iz.y + hz.y);
        float nn = tanhf(in_.y + r * hn.y);
        out.y = (1.f - z) * nn + z * h0.y;
    }
    {
        float r = sigmoidf_(ir.z + hr.z), z = sigmoidf_(iz.z + hz.z);
        float nn = tanhf(in_.z + r * hn.z);
        out.z = (1.f - z) * nn + z * h0.z;
    }
    {
        float r = sigmoidf_(ir.w + hr.w), z = sigmoidf_(iz.w + hz.w);
        float nn = tanhf(in_.w + r * hn.w);
        out.w = (1.f - z) * nn + z * h0.w;
    }
    ((float4*)h)[(size_t)n * 32 + g] = out;
}

// ---------------- output scatter: deterministic last-index-wins on collisions ----------------
__global__ void k_scat1(const int* __restrict__ nb, const int* __restrict__ ne,
                        int* __restrict__ winner, int n_ent)
{
    int n = blockIdx.x * blockDim.x + threadIdx.x;
    if (n >= N_NODE) return;
    size_t slot = (size_t)nb[n] * n_ent + ne[n];
    atomicMax(&winner[slot], n);
}

__global__ void k_scat2(const float* __restrict__ h, const float* __restrict__ Wfinal,
                        const int* __restrict__ nb, const int* __restrict__ ne,
                        const int* __restrict__ winner, float* __restrict__ out, int n_ent)
{
    int n = (int)((blockIdx.x * blockDim.x + threadIdx.x) >> 5);
    int lane = threadIdx.x & 31;
    if (n >= N_NODE) return;
    float4 hv = ((const float4*)h)[(size_t)n * 32 + lane];
    float4 wv = ((const float4*)Wfinal)[lane];
    float s = hv.x * wv.x + hv.y * wv.y + hv.z * wv.z + hv.w * wv.w;
#pragma unroll
    for (int off = 16; off; off >>= 1) s += __shfl_xor_sync(0xffffffffu, s, off);
    if (lane == 0) {
        size_t slot = (size_t)nb[n] * n_ent + ne[n];
        if (winner[slot] == n) out[slot] = s;
    }
}

// ---------------- host launcher ----------------
extern "C" void kernel_launch(void* const* d_in, const int* in_sizes, int n_in,
                              void* d_out, int out_size)
{
    const float* rela     = (const float*)d_in[0];
    const float* Ws       = (const float*)d_in[1];
    const float* Wr       = (const float*)d_in[2];
    const float* Wqr_w    = (const float*)d_in[3];
    const float* Wqr_b    = (const float*)d_in[4];
    const float* Wtau     = (const float*)d_in[5];
    const float* walpha_w = (const float*)d_in[6];
    const float* walpha_b = (const float*)d_in[7];
    const float* Wh       = (const float*)d_in[8];
    const float* wt1      = (const float*)d_in[9];
    const float* bt1      = (const float*)d_in[10];
    const float* wt2      = (const float*)d_in[11];
    const float* bt2      = (const float*)d_in[12];
    const float* Wih      = (const float*)d_in[13];
    const float* Whh      = (const float*)d_in[14];
    const float* bih      = (const float*)d_in[15];
    const float* bhh      = (const float*)d_in[16];
    const float* Wfinal   = (const float*)d_in[17];
    const int*   q_rel    = (const int*)d_in[18];
    const int*   q_tau    = (const int*)d_in[19];
    const int*   e_ridx   = (const int*)d_in[20];
    const int*   e_rel    = (const int*)d_in[21];
    const int*   e_tau    = (const int*)d_in[22];
    const int*   e_sub    = (const int*)d_in[23];
    const int*   e_obj    = (const int*)d_in[24];
    const int*   nb       = (const int*)d_in[25];
    const int*   ne       = (const int*)d_in[26];

    int nq    = in_sizes[18];
    int n_ent = out_size / nq;

    float *hprev, *hidden1, *agg, *gi, *gh, *HS, *Rattn, *Qattn, *Hattn, *Hmsg;
    int* winner;
    cudaGetSymbolAddress((void**)&hprev,   g_hprev);
    cudaGetSymbolAddress((void**)&hidden1, g_hidden1);
    cudaGetSymbolAddress((void**)&agg,     g_agg);
    cudaGetSymbolAddress((void**)&gi,      g_gi);
    cudaGetSymbolAddress((void**)&gh,      g_gh);
    cudaGetSymbolAddress((void**)&HS,      g_HS);
    cudaGetSymbolAddress((void**)&Rattn,   g_Rattn);
    cudaGetSymbolAddress((void**)&Qattn,   g_Qattn);
    cudaGetSymbolAddress((void**)&Hattn,   g_Hattn);
    cudaGetSymbolAddress((void**)&Hmsg,    g_Hmsg);
    cudaGetSymbolAddress((void**)&winner,  g_winner);

    cudaMemsetAsync(hprev, 0, sizeof(float) * (size_t)N_NODE * D_DIM);

    const int mblocks = (N_NODE + 127) / 128;   // 782
    dim3 gM1(mblocks, 1), gM3(mblocks, 3);

    for (int l = 0; l < L_LAYERS; l++) {
        cudaMemsetAsync(agg, 0, sizeof(float) * (size_t)N_NODE * D_DIM);

        k_tab_rq<<<NREL + NQ_C, 64>>>(rela + (size_t)l * NREL * 128,
                                      Wr + (size_t)l * 64 * 128,
                                      Wqr_w + (size_t)l * 64 * 128,
                                      Wqr_b + (size_t)l * 64,
                                      q_rel, Rattn, Qattn);
        k_tab_delta<<<N_DELTA, 128>>>(wt1 + (size_t)l * 128, bt1 + (size_t)l * 128,
                                      wt2 + (size_t)l * 128, bt2 + (size_t)l * 128,
                                      Wtau + (size_t)l * 64 * 128, Hmsg, Hattn);
        // HS = hprev @ Ws^T  [N_NODE, 64]
        k_sgemm<<<gM1, 256>>>(hprev, Ws + (size_t)l * 64 * 128, nullptr, HS, N_NODE, 64, 0);

        k_edge<<<N_EDGE / 8, 256>>>(e_sub + (size_t)l * N_EDGE, e_rel + (size_t)l * N_EDGE,
                                    e_obj + (size_t)l * N_EDGE, e_ridx + (size_t)l * N_EDGE,
                                    e_tau + (size_t)l * N_EDGE, q_tau,
                                    HS, Rattn, Qattn, Hattn, Hmsg, hprev,
                                    rela + (size_t)l * NREL * 128,
                                    walpha_w + (size_t)l * 64, walpha_b + l, agg);

        // hidden1 = relu(agg @ Wh^T)
        k_sgemm<<<gM1, 256>>>(agg, Wh + (size_t)l * 128 * 128, nullptr, hidden1, N_NODE, 128, 1);
        // gi = hidden1 @ Wih^T + bih
        k_sgemm<<<gM3, 256>>>(hidden1, Wih + (size_t)l * 384 * 128, bih + (size_t)l * 384,
                              gi, N_NODE, 384, 0);
        // gh = hprev @ Whh^T + bhh
        k_sgemm<<<gM3, 256>>>(hprev, Whh + (size_t)l * 384 * 128, bhh + (size_t)l * 384,
                              gh, N_NODE, 384, 0);
        // hprev <- GRU(hidden1-as-x via gi, hprev-as-h via gh)
        k_gru<<<(N_NODE * 32) / 256, 256>>>(gi, gh, hprev);
    }

    cudaMemsetAsync(d_out, 0, (size_t)out_size * sizeof(float));
    cudaMemsetAsync(winner, 0xFF, (size_t)out_size * sizeof(int));
    k_scat1<<<(N_NODE + 255) / 256, 256>>>(nb, ne, winner, n_ent);
    k_scat2<<<(N_NODE * 32) / 256, 256>>>(hprev, Wfinal, nb, ne, winner, (float*)d_out, n_ent);
}